// round 14
// baseline (speedup 1.0000x reference)
#include <cuda_runtime.h>
#include <cuda_pipeline.h>
#include <cstdint>

// Problem constants (fixed by the reference)
#define B 16
#define S 4096
#define H 768
#define NUM_WORDS 2048          // S/2
#define H4 (H / 4)              // 192 float4 lanes per row
#define TT 32                   // tokens owned per block
#define NT 128                  // blocks per batch row (covers tokens 1..4095)
#define WW (NUM_WORDS / NT)     // 16: static zero-fill words per block
#define T 5                     // tokens per pipeline stage (15 KB)
#define STG_F4 (T * H4)         // float4 elements per stage (960)
#define WIN (TT + 2)            // wid window: positions t0-1 .. t0+TT

// Fused single kernel, one block per (batch, 32-token chunk).
// The payload pipeline indexes from the STATIC t0 (not the data-dependent
// word start), so the first two cp.async stages are issued speculatively
// before word_ids is even read -> no serial prologue->payload dependency.
// Tokens in [t0, s_first) are loaded but not accumulated (they belong to the
// previous chunk's word). Pipeline is fully per-thread: each thread's
// cp.async writes only smem cells {j*H4 + tid} and only that thread reads
// them; no block barriers on the hot path.
__global__ __launch_bounds__(H4) void fused_word_mean_kernel(
    const float* __restrict__ hidden,   // [B, S, H]
    const int*   __restrict__ word_ids, // [B, S]
    float*       __restrict__ out)      // [B, NUM_WORDS, H]
{
    __shared__ float4 s_buf[2][STG_F4];     // 30 KB
    __shared__ int s_wid[WIN];
    __shared__ int s_endtab[TT];
    __shared__ int s_meta[4];               // nwords, s_first, w_first, e_last

    const int blk = blockIdx.x;
    const int b   = blk / NT;
    const int tc  = blk % NT;
    const int t0  = 1 + tc * TT;
    const int t_range_end = min(t0 + TT, S - 1);
    const int tid = threadIdx.x;            // 0..191
    const int* __restrict__ wrow = word_ids + b * S;

    // ---- SPECULATIVE: issue pipeline stages 0 and 1 from t0 immediately ----
    // Tokens t0 .. t0+2T-1 (max 4074 < S) are always in-bounds for row b.
    const float4* __restrict__ src =
        reinterpret_cast<const float4*>(hidden) + ((size_t)b * S + t0) * H4;
    #pragma unroll
    for (int i = 0; i < T; ++i)
        __pipeline_memcpy_async(&s_buf[0][i * H4 + tid], &src[i * H4 + tid],
                                sizeof(float4));
    __pipeline_commit();
    #pragma unroll
    for (int i = 0; i < T; ++i)
        __pipeline_memcpy_async(&s_buf[1][i * H4 + tid],
                                &src[(T + i) * H4 + tid], sizeof(float4));
    __pipeline_commit();

    // ---- load wid window [t0-1 .. t0+TT] (overlaps speculative loads) ----
    if (tid < WIN) {
        const int p = t0 - 1 + tid;
        s_wid[tid] = (p < S) ? wrow[p] : -1;
    }

    // ---- independent zero-fill for absent words (overlapped) ----
    const int wmax = __ldg(wrow + (S - 2));
    const int wz0  = tc * WW;
    if (wz0 + WW - 1 > wmax) {
        float4* __restrict__ zrow =
            reinterpret_cast<float4*>(out) + (size_t)b * NUM_WORDS * H4 + tid;
        const float4 z = make_float4(0.f, 0.f, 0.f, 0.f);
        #pragma unroll
        for (int k2 = 0; k2 < WW; ++k2) {
            const int w = wz0 + k2;
            if (w > wmax) __stcs(&zrow[(size_t)w * H4], z);
        }
    }
    __syncthreads();

    // ---- warp 0: build local boundary table (words STARTING in range) ----
    if (tid < 32) {
        const int i = tid;                   // token p = t0 + i
        const int p = t0 + i;
        const int w_i    = s_wid[i + 1];
        const int prev_i = s_wid[i];
        const bool is_start = (p < t_range_end) && (w_i != prev_i);
        const unsigned mask = __ballot_sync(0xffffffffu, is_start);
        const int nwords = __popc(mask);
        if (is_start) {
            const int rank = __popc(mask & ((1u << i) - 1));
            int end;
            const unsigned higher = mask & ~((i < 31) ? ((2u << i) - 1) : 0xffffffffu);
            if (higher) {
                end = t0 + __ffs(higher) - 1;     // next start = this word's end
            } else {
                // last word starting in range: scan forward (terminates at
                // latest at wid[S-1] == -1)
                int q = p + 1;
                while (true) {
                    const int wi = q - (t0 - 1);
                    const int wq = (wi < WIN) ? s_wid[wi] : __ldg(wrow + q);
                    if (wq != w_i) break;
                    ++q;
                }
                end = q;
            }
            s_endtab[rank] = end;
            if (rank == 0) { s_meta[1] = p; s_meta[2] = w_i; }
            if (rank == nwords - 1) s_meta[3] = end;
        }
        if (i == 0) s_meta[0] = nwords;
    }
    __syncthreads();    // table ready; last block-wide barrier

    const int nwords = s_meta[0];
    if (nwords <= 0) {                       // whole range inside one spanning word
        __pipeline_wait_prior(0);            // drain speculative groups
        return;
    }

    const int s_first = s_meta[1];
    const int w_first = s_meta[2];
    const int e_last  = s_meta[3];
    const int n_tok   = e_last - t0;         // pipeline indexed from t0

    float4* __restrict__ outBase =
        reinterpret_cast<float4*>(out) + ((size_t)b * NUM_WORDS + w_first) * H4 + tid;

    const int total_f4 = n_tok * H4;
    const int n_stages = (n_tok + T - 1) / T;

    int k = 0;
    int e_cur = s_endtab[0];
    int s_cur = s_first;
    float4 acc = make_float4(0.f, 0.f, 0.f, 0.f);

    for (int s = 0; s < n_stages; ++s) {
        // wait for THIS thread's stage-s group (exactly 1 newer group pending:
        // prologue committed 2; each iteration commits exactly 1)
        __pipeline_wait_prior(1);

        const float4* __restrict__ buf = s_buf[s & 1];
        #pragma unroll
        for (int j = 0; j < T; ++j) {
            const int t = t0 + s * T + j;
            if (t >= s_first && t < e_last) {   // uniform across block
                const float4 v = buf[j * H4 + tid];
                if (t == e_cur) {               // word k complete -> emit mean
                    const int c = e_cur - s_cur;
                    const float inv = __fdividef(1.0f, (float)c);
                    float4 r;
                    r.x = acc.x * inv; r.y = acc.y * inv;
                    r.z = acc.z * inv; r.w = acc.w * inv;
                    __stcs(&outBase[k * H4], r);
                    s_cur = e_cur;
                    ++k;
                    e_cur = s_endtab[k < nwords ? k : nwords - 1];
                    acc = make_float4(0.f, 0.f, 0.f, 0.f);
                }
                acc.x += v.x; acc.y += v.y;
                acc.z += v.z; acc.w += v.w;
            }
        }

        // refill buf[s&1] with stage s+2 (thread's own cells; reads retired).
        // Always commit one group to keep wait accounting uniform.
        if (s + 2 < n_stages) {
            float4* dst = s_buf[s & 1];
            const int base = (s + 2) * STG_F4;
            #pragma unroll
            for (int i = 0; i < T; ++i) {
                const int idx = i * H4 + tid;
                const int g   = base + idx;
                if (g < total_f4)
                    __pipeline_memcpy_async(&dst[idx], &src[g], sizeof(float4));
            }
        }
        __pipeline_commit();
    }

    // Last word (its end == e_last is never reached inside the loop).
    {
        const int c = e_last - s_cur;
        const float inv = __fdividef(1.0f, (float)(c > 0 ? c : 1));
        float4 r;
        r.x = acc.x * inv; r.y = acc.y * inv;
        r.z = acc.z * inv; r.w = acc.w * inv;
        __stcs(&outBase[(nwords - 1) * H4], r);
    }
    __pipeline_wait_prior(0);   // drain trailing (possibly empty) groups
}

extern "C" void kernel_launch(void* const* d_in, const int* in_sizes, int n_in,
                              void* d_out, int out_size)
{
    const float* hidden   = (const float*)d_in[0];  // [B,S,H] float32
    const int*   word_ids = (const int*)d_in[1];    // [B,S] int32
    float*       out      = (float*)d_out;          // [B,NUM_WORDS,H] float32

    (void)in_sizes; (void)n_in; (void)out_size;

    fused_word_mean_kernel<<<B * NT, H4>>>(hidden, word_ids, out);
}

// round 15
// speedup vs baseline: 1.0474x; 1.0474x over previous
#include <cuda_runtime.h>
#include <cuda_pipeline.h>
#include <cstdint>

// Problem constants (fixed by the reference)
#define B 16
#define S 4096
#define H 768
#define NUM_WORDS 2048          // S/2
#define H4 (H / 4)              // 192 float4 lanes per row
#define TT 32                   // tokens owned per block
#define NT 128                  // blocks per batch row (covers tokens 1..4095)
#define WW (NUM_WORDS / NT)     // 16: static zero-fill words per block
#define T 6                     // tokens per pipeline stage
#define STG_F4 (T * H4)         // float4 elements per stage (1152 = 18KB)
#define WIN (TT + 2)            // wid window: positions t0-1 .. t0+TT

// Fused single kernel, one block per (batch, 32-token chunk).
// Payload pipeline is fully PER-THREAD (no block barriers on the hot path):
// each thread's cp.async writes only smem cells {j*H4 + tid} and only that
// thread reads them; each thread waits only on its own commit groups.
__global__ __launch_bounds__(H4) void fused_word_mean_kernel(
    const float* __restrict__ hidden,   // [B, S, H]
    const int*   __restrict__ word_ids, // [B, S]
    float*       __restrict__ out)      // [B, NUM_WORDS, H]
{
    __shared__ float4 s_buf[2][STG_F4];     // 36 KB
    __shared__ int s_wid[WIN];
    __shared__ int s_endtab[TT];
    __shared__ int s_meta[4];               // nwords, s_first, w_first, e_last

    const int blk = blockIdx.x;
    const int b   = blk / NT;
    const int tc  = blk % NT;
    const int t0  = 1 + tc * TT;
    const int t_range_end = min(t0 + TT, S - 1);
    const int tid = threadIdx.x;            // 0..191
    const int* __restrict__ wrow = word_ids + b * S;

    // ---- load wid window [t0-1 .. t0+TT] ----
    if (tid < WIN) {
        const int p = t0 - 1 + tid;
        s_wid[tid] = (p < S) ? wrow[p] : -1;
    }

    // ---- independent zero-fill for absent words, overlapped with prologue ----
    const int wmax = __ldg(wrow + (S - 2));
    const int wz0  = tc * WW;
    if (wz0 + WW - 1 > wmax) {
        float4* __restrict__ zrow =
            reinterpret_cast<float4*>(out) + (size_t)b * NUM_WORDS * H4 + tid;
        const float4 z = make_float4(0.f, 0.f, 0.f, 0.f);
        #pragma unroll
        for (int k2 = 0; k2 < WW; ++k2) {
            const int w = wz0 + k2;
            if (w > wmax) __stcs(&zrow[(size_t)w * H4], z);
        }
    }
    __syncthreads();

    // ---- warp 0: build local boundary table (words STARTING in range) ----
    if (tid < 32) {
        const int i = tid;                   // token p = t0 + i
        const int p = t0 + i;
        const int w_i    = s_wid[i + 1];
        const int prev_i = s_wid[i];
        const bool is_start = (p < t_range_end) && (w_i != prev_i);
        const unsigned mask = __ballot_sync(0xffffffffu, is_start);
        const int nwords = __popc(mask);
        if (is_start) {
            const int rank = __popc(mask & ((1u << i) - 1));
            int end;
            const unsigned higher = mask & ~((i < 31) ? ((2u << i) - 1) : 0xffffffffu);
            if (higher) {
                end = t0 + __ffs(higher) - 1;     // next start = this word's end
            } else {
                // last word starting in range: scan forward (terminates at
                // latest at wid[S-1] == -1)
                int q = p + 1;
                while (true) {
                    const int wi = q - (t0 - 1);
                    const int wq = (wi < WIN) ? s_wid[wi] : __ldg(wrow + q);
                    if (wq != w_i) break;
                    ++q;
                }
                end = q;
            }
            s_endtab[rank] = end;
            if (rank == 0) { s_meta[1] = p; s_meta[2] = w_i; }
            if (rank == nwords - 1) s_meta[3] = end;
        }
        if (i == 0) s_meta[0] = nwords;
    }
    __syncthreads();    // table ready; last block-wide barrier

    const int nwords = s_meta[0];
    if (nwords <= 0) return;

    const int s_first = s_meta[1];
    const int w_first = s_meta[2];
    const int e_last  = s_meta[3];
    const int n_tok   = e_last - s_first;

    const float4* __restrict__ src =
        reinterpret_cast<const float4*>(hidden) + ((size_t)b * S + s_first) * H4;
    float4* __restrict__ outBase =
        reinterpret_cast<float4*>(out) + ((size_t)b * NUM_WORDS + w_first) * H4 + tid;

    const int total_f4 = n_tok * H4;
    const int n_stages = (n_tok + T - 1) / T;

    // ---- prime the per-thread pipeline: issue stages 0 and 1 ----
    #pragma unroll
    for (int i = 0; i < T; ++i) {
        const int idx = i * H4 + tid;
        if (idx < total_f4)
            __pipeline_memcpy_async(&s_buf[0][idx], &src[idx], sizeof(float4));
    }
    __pipeline_commit();
    if (n_stages > 1) {
        #pragma unroll
        for (int i = 0; i < T; ++i) {
            const int idx = i * H4 + tid;
            const int g   = STG_F4 + idx;
            if (g < total_f4)
                __pipeline_memcpy_async(&s_buf[1][idx], &src[g], sizeof(float4));
        }
        __pipeline_commit();
    }

    int k = 0;
    int e_cur = s_endtab[0];
    int s_cur = s_first;
    float4 acc = make_float4(0.f, 0.f, 0.f, 0.f);

    for (int s = 0; s < n_stages; ++s) {
        // wait for THIS thread's stage-s group only
        if (s + 1 < n_stages) __pipeline_wait_prior(1);
        else                  __pipeline_wait_prior(0);

        const float4* __restrict__ buf = s_buf[s & 1];
        #pragma unroll
        for (int j = 0; j < T; ++j) {
            const int t = s_first + s * T + j;
            if (t < e_last) {            // uniform across block
                const float4 v = buf[j * H4 + tid];
                if (t == e_cur) {        // word k complete -> emit mean
                    const int c = e_cur - s_cur;
                    const float inv = __fdividef(1.0f, (float)c);
                    float4 r;
                    r.x = acc.x * inv; r.y = acc.y * inv;
                    r.z = acc.z * inv; r.w = acc.w * inv;
                    __stcs(&outBase[k * H4], r);
                    s_cur = e_cur;
                    ++k;
                    e_cur = s_endtab[k < nwords ? k : nwords - 1];
                    acc = make_float4(0.f, 0.f, 0.f, 0.f);
                }
                acc.x += v.x; acc.y += v.y;
                acc.z += v.z; acc.w += v.w;
            }
        }

        // refill buf[s&1] with stage s+2 (this thread's own cells only;
        // its reads above are already retired before the data can land)
        if (s + 2 < n_stages) {
            float4* dst = s_buf[s & 1];
            const int base = (s + 2) * STG_F4;
            #pragma unroll
            for (int i = 0; i < T; ++i) {
                const int idx = i * H4 + tid;
                const int g   = base + idx;
                if (g < total_f4)
                    __pipeline_memcpy_async(&dst[idx], &src[g], sizeof(float4));
            }
            __pipeline_commit();
        }
    }

    // Last word (its end == e_last is never reached inside the loop).
    {
        const int c = e_last - s_cur;
        const float inv = __fdividef(1.0f, (float)(c > 0 ? c : 1));
        float4 r;
        r.x = acc.x * inv; r.y = acc.y * inv;
        r.z = acc.z * inv; r.w = acc.w * inv;
        __stcs(&outBase[(nwords - 1) * H4], r);
    }
}

extern "C" void kernel_launch(void* const* d_in, const int* in_sizes, int n_in,
                              void* d_out, int out_size)
{
    const float* hidden   = (const float*)d_in[0];  // [B,S,H] float32
    const int*   word_ids = (const int*)d_in[1];    // [B,S] int32
    float*       out      = (float*)d_out;          // [B,NUM_WORDS,H] float32

    (void)in_sizes; (void)n_in; (void)out_size;

    fused_word_mean_kernel<<<B * NT, H4>>>(hidden, word_ids, out);
}

// round 16
// speedup vs baseline: 1.0758x; 1.0271x over previous
#include <cuda_runtime.h>
#include <cuda_pipeline.h>
#include <cstdint>

// Problem constants (fixed by the reference)
#define B 16
#define S 4096
#define H 768
#define NUM_WORDS 2048          // S/2
#define H4 (H / 4)              // 192 float4 lanes per row
#define TT 32                   // tokens owned per block
#define NT 128                  // blocks per batch row (covers tokens 1..4095)
#define WW (NUM_WORDS / NT)     // 16: static zero-fill words per block
#define T 8                     // tokens per pipeline stage (24 KB)
#define STG_F4 (T * H4)         // float4 elements per stage (1536)
#define WIN (TT + 2)            // wid window: positions t0-1 .. t0+TT

// Fused single kernel, one block per (batch, 32-token chunk).
// Payload pipeline is fully PER-THREAD (no block barriers on the hot path):
// each thread's cp.async writes only smem cells {j*H4 + tid} and only that
// thread reads them; each thread waits only on its own commit groups.
__global__ __launch_bounds__(H4) void fused_word_mean_kernel(
    const float* __restrict__ hidden,   // [B, S, H]
    const int*   __restrict__ word_ids, // [B, S]
    float*       __restrict__ out)      // [B, NUM_WORDS, H]
{
    __shared__ float4 s_buf[2][STG_F4];     // 48 KB
    __shared__ int s_wid[WIN];
    __shared__ int s_endtab[TT];
    __shared__ int s_meta[4];               // nwords, s_first, w_first, e_last

    const int blk = blockIdx.x;
    const int b   = blk / NT;
    const int tc  = blk % NT;
    const int t0  = 1 + tc * TT;
    const int t_range_end = min(t0 + TT, S - 1);
    const int tid = threadIdx.x;            // 0..191
    const int* __restrict__ wrow = word_ids + b * S;

    // ---- load wid window [t0-1 .. t0+TT] ----
    if (tid < WIN) {
        const int p = t0 - 1 + tid;
        s_wid[tid] = (p < S) ? wrow[p] : -1;
    }

    // ---- independent zero-fill for absent words, overlapped with prologue ----
    const int wmax = __ldg(wrow + (S - 2));
    const int wz0  = tc * WW;
    if (wz0 + WW - 1 > wmax) {
        float4* __restrict__ zrow =
            reinterpret_cast<float4*>(out) + (size_t)b * NUM_WORDS * H4 + tid;
        const float4 z = make_float4(0.f, 0.f, 0.f, 0.f);
        #pragma unroll
        for (int k2 = 0; k2 < WW; ++k2) {
            const int w = wz0 + k2;
            if (w > wmax) __stcs(&zrow[(size_t)w * H4], z);
        }
    }
    __syncthreads();

    // ---- warp 0: build local boundary table (words STARTING in range) ----
    if (tid < 32) {
        const int i = tid;                   // token p = t0 + i
        const int p = t0 + i;
        const int w_i    = s_wid[i + 1];
        const int prev_i = s_wid[i];
        const bool is_start = (p < t_range_end) && (w_i != prev_i);
        const unsigned mask = __ballot_sync(0xffffffffu, is_start);
        const int nwords = __popc(mask);
        if (is_start) {
            const int rank = __popc(mask & ((1u << i) - 1));
            int end;
            const unsigned higher = mask & ~((i < 31) ? ((2u << i) - 1) : 0xffffffffu);
            if (higher) {
                end = t0 + __ffs(higher) - 1;     // next start = this word's end
            } else {
                // last word starting in range: scan forward (terminates at
                // latest at wid[S-1] == -1)
                int q = p + 1;
                while (true) {
                    const int wi = q - (t0 - 1);
                    const int wq = (wi < WIN) ? s_wid[wi] : __ldg(wrow + q);
                    if (wq != w_i) break;
                    ++q;
                }
                end = q;
            }
            s_endtab[rank] = end;
            if (rank == 0) { s_meta[1] = p; s_meta[2] = w_i; }
            if (rank == nwords - 1) s_meta[3] = end;
        }
        if (i == 0) s_meta[0] = nwords;
    }
    __syncthreads();    // table ready; last block-wide barrier

    const int nwords = s_meta[0];
    if (nwords <= 0) return;

    const int s_first = s_meta[1];
    const int w_first = s_meta[2];
    const int e_last  = s_meta[3];
    const int n_tok   = e_last - s_first;

    const float4* __restrict__ src =
        reinterpret_cast<const float4*>(hidden) + ((size_t)b * S + s_first) * H4;
    float4* __restrict__ outBase =
        reinterpret_cast<float4*>(out) + ((size_t)b * NUM_WORDS + w_first) * H4 + tid;

    const int total_f4 = n_tok * H4;
    const int n_stages = (n_tok + T - 1) / T;

    // ---- prime the per-thread pipeline: issue stages 0 and 1 ----
    #pragma unroll
    for (int i = 0; i < T; ++i) {
        const int idx = i * H4 + tid;
        if (idx < total_f4)
            __pipeline_memcpy_async(&s_buf[0][idx], &src[idx], sizeof(float4));
    }
    __pipeline_commit();
    if (n_stages > 1) {
        #pragma unroll
        for (int i = 0; i < T; ++i) {
            const int idx = i * H4 + tid;
            const int g   = STG_F4 + idx;
            if (g < total_f4)
                __pipeline_memcpy_async(&s_buf[1][idx], &src[g], sizeof(float4));
        }
        __pipeline_commit();
    }

    int k = 0;
    int e_cur = s_endtab[0];
    int s_cur = s_first;
    float4 acc = make_float4(0.f, 0.f, 0.f, 0.f);

    for (int s = 0; s < n_stages; ++s) {
        // wait for THIS thread's stage-s group only
        if (s + 1 < n_stages) __pipeline_wait_prior(1);
        else                  __pipeline_wait_prior(0);

        const float4* __restrict__ buf = s_buf[s & 1];
        #pragma unroll
        for (int j = 0; j < T; ++j) {
            const int t = s_first + s * T + j;
            if (t < e_last) {            // uniform across block
                const float4 v = buf[j * H4 + tid];
                if (t == e_cur) {        // word k complete -> emit mean
                    const int c = e_cur - s_cur;
                    const float inv = __fdividef(1.0f, (float)c);
                    float4 r;
                    r.x = acc.x * inv; r.y = acc.y * inv;
                    r.z = acc.z * inv; r.w = acc.w * inv;
                    __stcs(&outBase[k * H4], r);
                    s_cur = e_cur;
                    ++k;
                    e_cur = s_endtab[k < nwords ? k : nwords - 1];
                    acc = make_float4(0.f, 0.f, 0.f, 0.f);
                }
                acc.x += v.x; acc.y += v.y;
                acc.z += v.z; acc.w += v.w;
            }
        }

        // refill buf[s&1] with stage s+2 (this thread's own cells only;
        // its reads above are already retired before the data can land)
        if (s + 2 < n_stages) {
            float4* dst = s_buf[s & 1];
            const int base = (s + 2) * STG_F4;
            #pragma unroll
            for (int i = 0; i < T; ++i) {
                const int idx = i * H4 + tid;
                const int g   = base + idx;
                if (g < total_f4)
                    __pipeline_memcpy_async(&dst[idx], &src[g], sizeof(float4));
            }
            __pipeline_commit();
        }
    }

    // Last word (its end == e_last is never reached inside the loop).
    {
        const int c = e_last - s_cur;
        const float inv = __fdividef(1.0f, (float)(c > 0 ? c : 1));
        float4 r;
        r.x = acc.x * inv; r.y = acc.y * inv;
        r.z = acc.z * inv; r.w = acc.w * inv;
        __stcs(&outBase[(nwords - 1) * H4], r);
    }
}

extern "C" void kernel_launch(void* const* d_in, const int* in_sizes, int n_in,
                              void* d_out, int out_size)
{
    const float* hidden   = (const float*)d_in[0];  // [B,S,H] float32
    const int*   word_ids = (const int*)d_in[1];    // [B,S] int32
    float*       out      = (float*)d_out;          // [B,NUM_WORDS,H] float32

    (void)in_sizes; (void)n_in; (void)out_size;

    fused_word_mean_kernel<<<B * NT, H4>>>(hidden, word_ids, out);
}

// round 17
// speedup vs baseline: 1.1147x; 1.0361x over previous
#include <cuda_runtime.h>
#include <cuda_pipeline.h>
#include <cstdint>

// Problem constants (fixed by the reference)
#define B 16
#define S 4096
#define H 768
#define NUM_WORDS 2048          // S/2
#define H4 (H / 4)              // 192 float4 lanes per row
#define TT 64                   // tokens owned per block
#define NT 64                   // blocks per batch row (covers tokens 1..4095)
#define WW (NUM_WORDS / NT)     // 32: static zero-fill words per block
#define T 8                     // tokens per pipeline stage (24 KB)
#define STG_F4 (T * H4)         // float4 elements per stage (1536)
#define WIN (TT + 2)            // wid window: positions t0-1 .. t0+TT

// Fused single kernel, one block per (batch, 64-token chunk).
// Boundary table built by warp 0 with a 64-bit two-ballot start mask.
// Payload pipeline is fully PER-THREAD (no block barriers on the hot path):
// each thread's cp.async writes only smem cells {j*H4 + tid} and only that
// thread reads them; each thread waits only on its own commit groups.
__global__ __launch_bounds__(H4) void fused_word_mean_kernel(
    const float* __restrict__ hidden,   // [B, S, H]
    const int*   __restrict__ word_ids, // [B, S]
    float*       __restrict__ out)      // [B, NUM_WORDS, H]
{
    __shared__ float4 s_buf[2][STG_F4];     // 48 KB
    __shared__ int s_wid[WIN];
    __shared__ int s_endtab[TT];
    __shared__ int s_meta[4];               // nwords, s_first, w_first, e_last

    const int blk = blockIdx.x;
    const int b   = blk / NT;
    const int tc  = blk % NT;
    const int t0  = 1 + tc * TT;
    const int t_range_end = min(t0 + TT, S - 1);
    const int tid = threadIdx.x;            // 0..191
    const int* __restrict__ wrow = word_ids + b * S;

    // ---- load wid window [t0-1 .. t0+TT] ----
    if (tid < WIN) {
        const int p = t0 - 1 + tid;
        s_wid[tid] = (p < S) ? wrow[p] : -1;
    }

    // ---- independent zero-fill for absent words, overlapped with prologue ----
    const int wmax = __ldg(wrow + (S - 2));
    const int wz0  = tc * WW;
    if (wz0 + WW - 1 > wmax) {
        float4* __restrict__ zrow =
            reinterpret_cast<float4*>(out) + (size_t)b * NUM_WORDS * H4 + tid;
        const float4 z = make_float4(0.f, 0.f, 0.f, 0.f);
        #pragma unroll
        for (int k2 = 0; k2 < WW; ++k2) {
            const int w = wz0 + k2;
            if (w > wmax) __stcs(&zrow[(size_t)w * H4], z);
        }
    }
    __syncthreads();

    // ---- warp 0: build 64-wide boundary table (words STARTING in range) ----
    if (tid < 32) {
        // half 0: positions i = tid, half 1: positions i = tid + 32
        const int iA = tid;
        const int iB = tid + 32;
        const int pA = t0 + iA;
        const int pB = t0 + iB;
        const int wA = s_wid[iA + 1], prevA = s_wid[iA];
        const int wB = s_wid[iB + 1], prevB = s_wid[iB];
        const bool stA = (pA < t_range_end) && (wA != prevA);
        const bool stB = (pB < t_range_end) && (wB != prevB);
        const unsigned mA = __ballot_sync(0xffffffffu, stA);
        const unsigned mB = __ballot_sync(0xffffffffu, stB);
        const unsigned long long mask =
            (unsigned long long)mA | ((unsigned long long)mB << 32);
        const int nwords = __popcll(mask);

        // process this lane's (up to two) start positions
        #pragma unroll
        for (int h = 0; h < 2; ++h) {
            const bool is_start = h ? stB : stA;
            if (!is_start) continue;
            const int i   = h ? iB : iA;
            const int p   = h ? pB : pA;
            const int w_i = h ? wB : wA;
            const int rank =
                (int)__popcll(mask & ((i == 0) ? 0ull : (~0ull >> (64 - i))));
            int end;
            const unsigned long long higher =
                (i == 63) ? 0ull : (mask & (~0ull << (i + 1)));
            if (higher) {
                end = t0 + __ffsll((long long)higher) - 1;  // next start
            } else {
                // last word starting in range: scan forward (terminates at
                // latest at wid[S-1] == -1)
                int q = p + 1;
                while (true) {
                    const int wi = q - (t0 - 1);
                    const int wq = (wi < WIN) ? s_wid[wi] : __ldg(wrow + q);
                    if (wq != w_i) break;
                    ++q;
                }
                end = q;
            }
            s_endtab[rank] = end;
            if (rank == 0) { s_meta[1] = p; s_meta[2] = w_i; }
            if (rank == nwords - 1) s_meta[3] = end;
        }
        if (tid == 0) s_meta[0] = nwords;
    }
    __syncthreads();    // table ready; last block-wide barrier

    const int nwords = s_meta[0];
    if (nwords <= 0) return;

    const int s_first = s_meta[1];
    const int w_first = s_meta[2];
    const int e_last  = s_meta[3];
    const int n_tok   = e_last - s_first;

    const float4* __restrict__ src =
        reinterpret_cast<const float4*>(hidden) + ((size_t)b * S + s_first) * H4;
    float4* __restrict__ outBase =
        reinterpret_cast<float4*>(out) + ((size_t)b * NUM_WORDS + w_first) * H4 + tid;

    const int total_f4 = n_tok * H4;
    const int n_stages = (n_tok + T - 1) / T;

    // ---- prime the per-thread pipeline: issue stages 0 and 1 ----
    #pragma unroll
    for (int i = 0; i < T; ++i) {
        const int idx = i * H4 + tid;
        if (idx < total_f4)
            __pipeline_memcpy_async(&s_buf[0][idx], &src[idx], sizeof(float4));
    }
    __pipeline_commit();
    if (n_stages > 1) {
        #pragma unroll
        for (int i = 0; i < T; ++i) {
            const int idx = i * H4 + tid;
            const int g   = STG_F4 + idx;
            if (g < total_f4)
                __pipeline_memcpy_async(&s_buf[1][idx], &src[g], sizeof(float4));
        }
        __pipeline_commit();
    }

    int k = 0;
    int e_cur = s_endtab[0];
    int s_cur = s_first;
    float4 acc = make_float4(0.f, 0.f, 0.f, 0.f);

    for (int s = 0; s < n_stages; ++s) {
        // wait for THIS thread's stage-s group only
        if (s + 1 < n_stages) __pipeline_wait_prior(1);
        else                  __pipeline_wait_prior(0);

        const float4* __restrict__ buf = s_buf[s & 1];
        #pragma unroll
        for (int j = 0; j < T; ++j) {
            const int t = s_first + s * T + j;
            if (t < e_last) {            // uniform across block
                const float4 v = buf[j * H4 + tid];
                if (t == e_cur) {        // word k complete -> emit mean
                    const int c = e_cur - s_cur;
                    const float inv = __fdividef(1.0f, (float)c);
                    float4 r;
                    r.x = acc.x * inv; r.y = acc.y * inv;
                    r.z = acc.z * inv; r.w = acc.w * inv;
                    __stcs(&outBase[k * H4], r);
                    s_cur = e_cur;
                    ++k;
                    e_cur = s_endtab[k < nwords ? k : nwords - 1];
                    acc = make_float4(0.f, 0.f, 0.f, 0.f);
                }
                acc.x += v.x; acc.y += v.y;
                acc.z += v.z; acc.w += v.w;
            }
        }

        // refill buf[s&1] with stage s+2 (this thread's own cells only;
        // its reads above are already retired before the data can land)
        if (s + 2 < n_stages) {
            float4* dst = s_buf[s & 1];
            const int base = (s + 2) * STG_F4;
            #pragma unroll
            for (int i = 0; i < T; ++i) {
                const int idx = i * H4 + tid;
                const int g   = base + idx;
                if (g < total_f4)
                    __pipeline_memcpy_async(&dst[idx], &src[g], sizeof(float4));
            }
            __pipeline_commit();
        }
    }

    // Last word (its end == e_last is never reached inside the loop).
    {
        const int c = e_last - s_cur;
        const float inv = __fdividef(1.0f, (float)(c > 0 ? c : 1));
        float4 r;
        r.x = acc.x * inv; r.y = acc.y * inv;
        r.z = acc.z * inv; r.w = acc.w * inv;
        __stcs(&outBase[(nwords - 1) * H4], r);
    }
}

extern "C" void kernel_launch(void* const* d_in, const int* in_sizes, int n_in,
                              void* d_out, int out_size)
{
    const float* hidden   = (const float*)d_in[0];  // [B,S,H] float32
    const int*   word_ids = (const int*)d_in[1];    // [B,S] int32
    float*       out      = (float*)d_out;          // [B,NUM_WORDS,H] float32

    (void)in_sizes; (void)n_in; (void)out_size;

    fused_word_mean_kernel<<<B * NT, H4>>>(hidden, word_ids, out);
}